// round 1
// baseline (speedup 1.0000x reference)
#include <cuda_runtime.h>
#include <math_constants.h>
#include <cstdint>
#include <cstddef>

// Problem constants
#define BB 2
#define NQ 4096
#define NKV 1024
#define DD 512
#define HH 8
#define DH 64
#define DS 4
#define LN_EPS 1e-5f

// ---------------------------------------------------------------------------
// Scratch (device globals; no allocation allowed)
// ---------------------------------------------------------------------------
__device__ float g_qh[BB * NQ * DD];      // q @ Wq
__device__ float g_kh[BB * NKV * DD];     // kv @ Wk
__device__ float g_vh[BB * NKV * DD];     // kv @ Wv
__device__ float g_attn[BB * NQ * DD];    // attention output (pre-LN)
__device__ float g_norm[BB * NQ * DD];    // LayerNorm output

// ---------------------------------------------------------------------------
// SGEMM: C[M,N] = A[M,K] @ W[K,N] (+ bias). 128x128 block tile, 8x8 thread
// tile, BK=8, 256 threads. All dims are multiples of the tile sizes here.
// ---------------------------------------------------------------------------
template <bool BIAS>
__global__ void __launch_bounds__(256) sgemm_kernel(
    const float* __restrict__ A, const float* __restrict__ W,
    const float* __restrict__ bias, float* __restrict__ C,
    int M, int N, int K)
{
    __shared__ float As[8][128];
    __shared__ float Bs[8][128];

    const int tid = threadIdx.x;
    const int tx = tid & 15;        // 0..15 -> N direction
    const int ty = tid >> 4;        // 0..15 -> M direction
    const int row0 = blockIdx.y * 128;
    const int col0 = blockIdx.x * 128;

    // A tile loader: 128 rows x 8 cols = 256 float4
    const int a_row = tid >> 1;
    const int a_k   = (tid & 1) << 2;
    // B tile loader: 8 rows x 128 cols = 256 float4
    const int b_k   = tid >> 5;
    const int b_col = (tid & 31) << 2;

    const float* Ap = A + (size_t)(row0 + a_row) * K + a_k;
    const float* Wp = W + (size_t)b_k * N + col0 + b_col;

    float acc[8][8];
    #pragma unroll
    for (int i = 0; i < 8; i++)
        #pragma unroll
        for (int j = 0; j < 8; j++) acc[i][j] = 0.f;

    for (int k0 = 0; k0 < K; k0 += 8) {
        float4 av = *(const float4*)Ap;
        float4 wv = *(const float4*)Wp;
        Ap += 8;
        Wp += (size_t)8 * N;

        As[a_k + 0][a_row] = av.x;
        As[a_k + 1][a_row] = av.y;
        As[a_k + 2][a_row] = av.z;
        As[a_k + 3][a_row] = av.w;
        *(float4*)&Bs[b_k][b_col] = wv;
        __syncthreads();

        #pragma unroll
        for (int kk = 0; kk < 8; kk++) {
            float af[8], bf[8];
            *(float4*)&af[0] = *(const float4*)&As[kk][ty * 8];
            *(float4*)&af[4] = *(const float4*)&As[kk][ty * 8 + 4];
            *(float4*)&bf[0] = *(const float4*)&Bs[kk][tx * 8];
            *(float4*)&bf[4] = *(const float4*)&Bs[kk][tx * 8 + 4];
            #pragma unroll
            for (int i = 0; i < 8; i++)
                #pragma unroll
                for (int j = 0; j < 8; j++)
                    acc[i][j] = fmaf(af[i], bf[j], acc[i][j]);
        }
        __syncthreads();
    }

    #pragma unroll
    for (int i = 0; i < 8; i++) {
        const size_t row = (size_t)(row0 + ty * 8 + i);
        float* Cp = C + row * N + col0 + tx * 8;
        #pragma unroll
        for (int j4 = 0; j4 < 8; j4 += 4) {
            float4 v;
            v.x = acc[i][j4 + 0];
            v.y = acc[i][j4 + 1];
            v.z = acc[i][j4 + 2];
            v.w = acc[i][j4 + 3];
            if (BIAS) {
                const float* bp = bias + col0 + tx * 8 + j4;
                v.x += bp[0]; v.y += bp[1]; v.z += bp[2]; v.w += bp[3];
            }
            *(float4*)(Cp + j4) = v;
        }
    }
}

// ---------------------------------------------------------------------------
// Flash attention with block-causal mask (key j allowed iff j <= i/DS).
// One block = 64 queries for one (b, h). 256 threads as 16(ty: 4 queries each)
// x 16(tx: 4 keys / 4 dims each). Key chunks of 64, online softmax.
// smem: Qs[64][64], KsT[64][68] (d-major, padded), Vs[64][64], Ps[64][64].
// ---------------------------------------------------------------------------
#define KST_STRIDE 68
#define ATTN_SMEM_FLOATS (64 * 64 + 64 * KST_STRIDE + 64 * 64 + 64 * 64)

__global__ void __launch_bounds__(256) attn_kernel(
    const float* __restrict__ Qh, const float* __restrict__ Kh,
    const float* __restrict__ Vh, float* __restrict__ O)
{
    extern __shared__ float sm[];
    float* Qs  = sm;                       // [64][64]
    float* KsT = Qs + 64 * 64;             // [64][KST_STRIDE], d-major
    float* Vs  = KsT + 64 * KST_STRIDE;    // [64][64]
    float* Ps  = Vs + 64 * 64;             // [64][64]

    const int qt = blockIdx.x;   // query tile (64 queries)
    const int h  = blockIdx.y;
    const int b  = blockIdx.z;
    const int tid = threadIdx.x;
    const int tx = tid & 15;
    const int ty = tid >> 4;

    const float scale = 0.125f;  // DH^-0.5 = 1/8

    const size_t qbase = ((size_t)b * NQ + (size_t)qt * 64) * DD + (size_t)h * DH;
    const size_t kbase = ((size_t)b * NKV) * DD + (size_t)h * DH;

    // Load Q tile (64x64) vectorized
    for (int i = tid; i < 64 * 16; i += 256) {
        const int q = i >> 4, d4 = (i & 15) << 2;
        *(float4*)&Qs[q * 64 + d4] =
            *(const float4*)&Qh[qbase + (size_t)q * DD + d4];
    }

    float m_[4], l_[4], o_[4][4];
    #pragma unroll
    for (int qq = 0; qq < 4; qq++) {
        m_[qq] = -CUDART_INF_F;
        l_[qq] = 0.f;
        #pragma unroll
        for (int dd = 0; dd < 4; dd++) o_[qq][dd] = 0.f;
    }

    // keys needed: j <= (qt*64+63)/4 = qt*16+15  -> kmax = qt*16+16 exclusive
    const int kmax = qt * 16 + 16;
    const int nchunks = (kmax + 63) >> 6;

    __syncthreads();

    for (int c = 0; c < nchunks; c++) {
        const int k0 = c * 64;

        // K tile, stored d-major (transposed) with pad-68 rows
        for (int i = tid; i < 4096; i += 256) {
            const int kk = i >> 6, d = i & 63;     // coalesced gmem read over d
            KsT[d * KST_STRIDE + kk] = Kh[kbase + (size_t)(k0 + kk) * DD + d];
        }
        // V tile, natural layout, vectorized
        for (int i = tid; i < 64 * 16; i += 256) {
            const int kk = i >> 4, d4 = (i & 15) << 2;
            *(float4*)&Vs[kk * 64 + d4] =
                *(const float4*)&Vh[kbase + (size_t)(k0 + kk) * DD + d4];
        }
        __syncthreads();

        // Scores: s[qq][kk] = Q[4ty+qq] . K[k0+4tx+kk]
        float s[4][4];
        #pragma unroll
        for (int qq = 0; qq < 4; qq++)
            #pragma unroll
            for (int kk = 0; kk < 4; kk++) s[qq][kk] = 0.f;

        #pragma unroll 16
        for (int d = 0; d < 64; d++) {
            const float4 kv = *(const float4*)&KsT[d * KST_STRIDE + tx * 4];
            #pragma unroll
            for (int qq = 0; qq < 4; qq++) {
                const float qv = Qs[(ty * 4 + qq) * 64 + d];
                s[qq][0] = fmaf(qv, kv.x, s[qq][0]);
                s[qq][1] = fmaf(qv, kv.y, s[qq][1]);
                s[qq][2] = fmaf(qv, kv.z, s[qq][2]);
                s[qq][3] = fmaf(qv, kv.w, s[qq][3]);
            }
        }

        // Mask + online softmax update (row stats across the 16 lanes of ty)
        #pragma unroll
        for (int qq = 0; qq < 4; qq++) {
            const int qg  = qt * 64 + ty * 4 + qq;
            const int lim = qg >> 2;               // allowed: key <= lim
            float mc = -CUDART_INF_F;
            #pragma unroll
            for (int kk = 0; kk < 4; kk++) {
                const int kg = k0 + tx * 4 + kk;
                s[qq][kk] = (kg <= lim) ? s[qq][kk] * scale : -CUDART_INF_F;
                mc = fmaxf(mc, s[qq][kk]);
            }
            mc = fmaxf(mc, __shfl_xor_sync(0xffffffffu, mc, 1));
            mc = fmaxf(mc, __shfl_xor_sync(0xffffffffu, mc, 2));
            mc = fmaxf(mc, __shfl_xor_sync(0xffffffffu, mc, 4));
            mc = fmaxf(mc, __shfl_xor_sync(0xffffffffu, mc, 8));

            const float mn = fmaxf(m_[qq], mc);
            const float alpha = __expf(m_[qq] - mn);
            m_[qq] = mn;

            float rs = 0.f;
            #pragma unroll
            for (int kk = 0; kk < 4; kk++) {
                const float p = __expf(s[qq][kk] - mn);
                s[qq][kk] = p;
                rs += p;
            }
            rs += __shfl_xor_sync(0xffffffffu, rs, 1);
            rs += __shfl_xor_sync(0xffffffffu, rs, 2);
            rs += __shfl_xor_sync(0xffffffffu, rs, 4);
            rs += __shfl_xor_sync(0xffffffffu, rs, 8);

            l_[qq] = l_[qq] * alpha + rs;
            #pragma unroll
            for (int dd = 0; dd < 4; dd++) o_[qq][dd] *= alpha;

            float4 pv;
            pv.x = s[qq][0]; pv.y = s[qq][1]; pv.z = s[qq][2]; pv.w = s[qq][3];
            *(float4*)&Ps[(ty * 4 + qq) * 64 + tx * 4] = pv;
        }
        __syncthreads();

        // O += P @ V  (thread tile: 4 queries x 4 dims at tx*4)
        #pragma unroll 16
        for (int k = 0; k < 64; k++) {
            const float4 vv = *(const float4*)&Vs[k * 64 + tx * 4];
            #pragma unroll
            for (int qq = 0; qq < 4; qq++) {
                const float p = Ps[(ty * 4 + qq) * 64 + k];
                o_[qq][0] = fmaf(p, vv.x, o_[qq][0]);
                o_[qq][1] = fmaf(p, vv.y, o_[qq][1]);
                o_[qq][2] = fmaf(p, vv.z, o_[qq][2]);
                o_[qq][3] = fmaf(p, vv.w, o_[qq][3]);
            }
        }
        __syncthreads();
    }

    // Epilogue: normalize and write out (b, q, h*64 + d)
    #pragma unroll
    for (int qq = 0; qq < 4; qq++) {
        const float inv = 1.f / l_[qq];
        float4 v;
        v.x = o_[qq][0] * inv;
        v.y = o_[qq][1] * inv;
        v.z = o_[qq][2] * inv;
        v.w = o_[qq][3] * inv;
        *(float4*)&O[qbase + (size_t)(ty * 4 + qq) * DD + tx * 4] = v;
    }
}

// ---------------------------------------------------------------------------
// LayerNorm over last dim (512). One block per row, 256 threads x 2 elems.
// ---------------------------------------------------------------------------
__global__ void __launch_bounds__(256) ln_kernel(
    const float* __restrict__ X, const float* __restrict__ gamma,
    const float* __restrict__ beta, float* __restrict__ Y)
{
    __shared__ float red[16];
    __shared__ float mv[2];

    const int row = blockIdx.x;
    const int tid = threadIdx.x;
    const float* x = X + (size_t)row * DD;

    const float2 v = *(const float2*)(x + tid * 2);
    float s  = v.x + v.y;
    float sq = v.x * v.x + v.y * v.y;

    #pragma unroll
    for (int off = 16; off > 0; off >>= 1) {
        s  += __shfl_xor_sync(0xffffffffu, s, off);
        sq += __shfl_xor_sync(0xffffffffu, sq, off);
    }
    const int wid = tid >> 5;
    if ((tid & 31) == 0) { red[wid] = s; red[8 + wid] = sq; }
    __syncthreads();
    if (tid == 0) {
        float S = 0.f, SQ = 0.f;
        #pragma unroll
        for (int w = 0; w < 8; w++) { S += red[w]; SQ += red[8 + w]; }
        const float mean = S * (1.f / DD);
        const float var  = SQ * (1.f / DD) - mean * mean;
        mv[0] = mean;
        mv[1] = rsqrtf(var + LN_EPS);
    }
    __syncthreads();
    const float mean = mv[0], r = mv[1];

    const float2 g = *(const float2*)(gamma + tid * 2);
    const float2 be = *(const float2*)(beta + tid * 2);
    float2 out;
    out.x = (v.x - mean) * r * g.x + be.x;
    out.y = (v.y - mean) * r * g.y + be.y;
    *(float2*)(Y + (size_t)row * DD + tid * 2) = out;
}

// ---------------------------------------------------------------------------
// Launch
// ---------------------------------------------------------------------------
extern "C" void kernel_launch(void* const* d_in, const int* in_sizes, int n_in,
                              void* d_out, int out_size)
{
    (void)in_sizes; (void)n_in; (void)out_size;

    const float* q     = (const float*)d_in[0];
    const float* kv    = (const float*)d_in[1];
    const float* Wq    = (const float*)d_in[2];
    const float* Wk    = (const float*)d_in[3];
    const float* Wv    = (const float*)d_in[4];
    const float* Wo    = (const float*)d_in[5];
    const float* bo    = (const float*)d_in[6];
    const float* gamma = (const float*)d_in[7];
    const float* beta  = (const float*)d_in[8];
    float* out = (float*)d_out;

    float *qh, *kh, *vh, *attn, *norm;
    cudaGetSymbolAddress((void**)&qh,   g_qh);
    cudaGetSymbolAddress((void**)&kh,   g_kh);
    cudaGetSymbolAddress((void**)&vh,   g_vh);
    cudaGetSymbolAddress((void**)&attn, g_attn);
    cudaGetSymbolAddress((void**)&norm, g_norm);

    const int attn_smem = ATTN_SMEM_FLOATS * (int)sizeof(float);
    cudaFuncSetAttribute(attn_kernel,
                         cudaFuncAttributeMaxDynamicSharedMemorySize, attn_smem);

    const int MQ = BB * NQ;    // 8192
    const int MK = BB * NKV;   // 2048

    // Projections
    {
        dim3 grid(DD / 128, MQ / 128);
        sgemm_kernel<false><<<grid, 256>>>(q, Wq, nullptr, qh, MQ, DD, DD);
    }
    {
        dim3 grid(DD / 128, MK / 128);
        sgemm_kernel<false><<<grid, 256>>>(kv, Wk, nullptr, kh, MK, DD, DD);
        sgemm_kernel<false><<<grid, 256>>>(kv, Wv, nullptr, vh, MK, DD, DD);
    }

    // Attention
    {
        dim3 grid(NQ / 64, HH, BB);
        attn_kernel<<<grid, 256, attn_smem>>>(qh, kh, vh, attn);
    }

    // LayerNorm
    ln_kernel<<<MQ, 256>>>(attn, gamma, beta, norm);

    // Output projection + bias
    {
        dim3 grid(DD / 128, MQ / 128);
        sgemm_kernel<true><<<grid, 256>>>(norm, Wo, bo, out, MQ, DD, DD);
    }
}

// round 2
// speedup vs baseline: 3.2376x; 3.2376x over previous
#include <cuda_runtime.h>
#include <math_constants.h>
#include <cstdint>
#include <cstddef>

#define BB 2
#define NQ 4096
#define NKV 1024
#define DD 512
#define HH 8
#define DH 64
#define LN_EPS 1e-5f

// ---------------------------------------------------------------------------
// Scratch
// ---------------------------------------------------------------------------
__device__ float g_qh[BB * NQ * DD];
__device__ float g_kh[BB * NKV * DD];
__device__ float g_vh[BB * NKV * DD];
__device__ float g_attn[BB * NQ * DD];
__device__ float g_norm[BB * NQ * DD];

// ---------------------------------------------------------------------------
// tf32 helpers
// ---------------------------------------------------------------------------
__device__ __forceinline__ uint32_t f2tf32(float x) {
    uint32_t r;
    asm("cvt.rna.tf32.f32 %0, %1;" : "=r"(r) : "f"(x));
    return r;
}

__device__ __forceinline__ void mma_tf32(float d[4], const uint32_t a[4],
                                         const uint32_t b[2]) {
    asm("mma.sync.aligned.m16n8k8.row.col.f32.tf32.tf32.f32 "
        "{%0,%1,%2,%3},{%4,%5,%6,%7},{%8,%9},{%0,%1,%2,%3};"
        : "+f"(d[0]), "+f"(d[1]), "+f"(d[2]), "+f"(d[3])
        : "r"(a[0]), "r"(a[1]), "r"(a[2]), "r"(a[3]), "r"(b[0]), "r"(b[1]));
}

// ---------------------------------------------------------------------------
// tf32 GEMM: C = A[M,K] @ W[K,N] (+bias).  BM=128 BN=128 BK=32, 256 threads.
// Warps 4(M) x 2(N), warp tile 32x64 (2 m-tiles x 8 n-tiles of m16n8k8).
// As stride 36 (k-fast), Bs stride 136 (n-fast): conflict-free frag loads.
// blockIdx.z selects (W0,C0) or (W1,C1) so K/V projections share one launch.
// ---------------------------------------------------------------------------
template <bool BIAS>
__global__ void __launch_bounds__(256) gemm_tf32(
    const float* __restrict__ A, const float* __restrict__ W0,
    const float* __restrict__ W1, const float* __restrict__ bias,
    float* __restrict__ C0, float* __restrict__ C1, int M, int N, int K)
{
    __shared__ uint32_t As[128 * 36];
    __shared__ uint32_t Bs[32 * 136];

    const float* __restrict__ W = blockIdx.z ? W1 : W0;
    float* __restrict__ C = blockIdx.z ? C1 : C0;

    const int tid = threadIdx.x;
    const int lane = tid & 31;
    const int g = lane >> 2, t = lane & 3;
    const int w = tid >> 5;
    const int wm = w >> 1, wn = w & 1;
    const int row0 = blockIdx.y * 128, col0 = blockIdx.x * 128;

    // gmem load geometry
    const int ar = tid >> 3;            // + i*32
    const int ak = (tid & 7) * 4;
    const int bk = tid >> 5;            // + i*8
    const int bn = (tid & 31) * 4;

    float4 aR[4], bR[4];

    auto loadA = [&](int k0) {
        #pragma unroll
        for (int i = 0; i < 4; i++)
            aR[i] = *(const float4*)(A + (size_t)(row0 + ar + i * 32) * K + k0 + ak);
    };
    auto loadB = [&](int k0) {
        #pragma unroll
        for (int i = 0; i < 4; i++)
            bR[i] = *(const float4*)(W + (size_t)(k0 + bk + i * 8) * N + col0 + bn);
    };

    float acc[2][8][4];
    #pragma unroll
    for (int mi = 0; mi < 2; mi++)
        #pragma unroll
        for (int ni = 0; ni < 8; ni++)
            #pragma unroll
            for (int r = 0; r < 4; r++) acc[mi][ni][r] = 0.f;

    loadA(0);
    loadB(0);

    for (int k0 = 0; k0 < K; k0 += 32) {
        // stage to smem (tf32 rounding applied here)
        #pragma unroll
        for (int i = 0; i < 4; i++) {
            uint32_t* p = &As[(ar + i * 32) * 36 + ak];
            p[0] = f2tf32(aR[i].x); p[1] = f2tf32(aR[i].y);
            p[2] = f2tf32(aR[i].z); p[3] = f2tf32(aR[i].w);
            uint32_t* q = &Bs[(bk + i * 8) * 136 + bn];
            q[0] = f2tf32(bR[i].x); q[1] = f2tf32(bR[i].y);
            q[2] = f2tf32(bR[i].z); q[3] = f2tf32(bR[i].w);
        }
        __syncthreads();

        if (k0 + 32 < K) { loadA(k0 + 32); loadB(k0 + 32); }

        #pragma unroll
        for (int ks = 0; ks < 4; ks++) {
            const int kk = ks * 8;
            uint32_t af[2][4];
            #pragma unroll
            for (int mi = 0; mi < 2; mi++) {
                const int mb = wm * 32 + mi * 16;
                af[mi][0] = As[(mb + g) * 36 + kk + t];
                af[mi][1] = As[(mb + g + 8) * 36 + kk + t];
                af[mi][2] = As[(mb + g) * 36 + kk + t + 4];
                af[mi][3] = As[(mb + g + 8) * 36 + kk + t + 4];
            }
            #pragma unroll
            for (int ni = 0; ni < 8; ni++) {
                const int nb = wn * 64 + ni * 8;
                uint32_t bf[2];
                bf[0] = Bs[(kk + t) * 136 + nb + g];
                bf[1] = Bs[(kk + t + 4) * 136 + nb + g];
                mma_tf32(acc[0][ni], af[0], bf);
                mma_tf32(acc[1][ni], af[1], bf);
            }
        }
        __syncthreads();
    }

    // epilogue
    #pragma unroll
    for (int mi = 0; mi < 2; mi++) {
        const int rr0 = row0 + wm * 32 + mi * 16 + g;
        #pragma unroll
        for (int ni = 0; ni < 8; ni++) {
            const int cc = col0 + wn * 64 + ni * 8 + 2 * t;
            float2 v0 = make_float2(acc[mi][ni][0], acc[mi][ni][1]);
            float2 v1 = make_float2(acc[mi][ni][2], acc[mi][ni][3]);
            if (BIAS) {
                const float2 bv = *(const float2*)(bias + cc);
                v0.x += bv.x; v0.y += bv.y;
                v1.x += bv.x; v1.y += bv.y;
            }
            *(float2*)(C + (size_t)rr0 * N + cc) = v0;
            *(float2*)(C + (size_t)(rr0 + 8) * N + cc) = v1;
        }
    }
}

// ---------------------------------------------------------------------------
// Flash attention, tf32 MMA. Block = 128 queries x one (b,h). 8 warps, each
// owning 16 complete query rows (softmax fully intra-warp). Key chunks of 64.
// Qs[128][68] (k-fast), Ks[64][72] = K^T (d-major), Vs[64][72] (d-fast).
// P stays in registers; C-frag -> A-frag remap via 8 shuffles per k-tile.
// Only the diagonal chunk needs masking (proved for this tiling).
// ---------------------------------------------------------------------------
#define ATTN_SMEM_BYTES ((128 * 68 + 64 * 72 + 64 * 72) * 4)

__global__ void __launch_bounds__(256) attn_mma(
    const float* __restrict__ Qh, const float* __restrict__ Kh,
    const float* __restrict__ Vh, float* __restrict__ O)
{
    extern __shared__ uint32_t sm[];
    uint32_t* Qs = sm;                  // 128 x 68
    uint32_t* Ks = Qs + 128 * 68;       // 64 x 72, [d][j]
    uint32_t* Vs = Ks + 64 * 72;        // 64 x 72, [j][d]

    const int tile = (NQ / 128 - 1) - blockIdx.x;   // big tiles first
    const int h = blockIdx.y, b = blockIdx.z;
    const int tid = threadIdx.x;
    const int lane = tid & 31;
    const int g = lane >> 2, t = lane & 3;
    const int w = tid >> 5;

    const size_t qbase = ((size_t)b * NQ + (size_t)tile * 128) * DD + (size_t)h * DH;
    const size_t kvbase = (size_t)b * NKV * DD + (size_t)h * DH;

    // Q tile: scale by 1/8 (exact), round to tf32
    #pragma unroll
    for (int i = 0; i < 8; i++) {
        const int idx = tid + i * 256;
        const int r = idx >> 4, c4 = (idx & 15) << 2;
        const float4 v = *(const float4*)(Qh + qbase + (size_t)r * DD + c4);
        uint4 u;
        u.x = f2tf32(v.x * 0.125f); u.y = f2tf32(v.y * 0.125f);
        u.z = f2tf32(v.z * 0.125f); u.w = f2tf32(v.w * 0.125f);
        *(uint4*)&Qs[r * 68 + c4] = u;
    }

    float oacc[8][4];
    #pragma unroll
    for (int ni = 0; ni < 8; ni++)
        #pragma unroll
        for (int r = 0; r < 4; r++) oacc[ni][r] = 0.f;
    float m0 = -CUDART_INF_F, m1 = -CUDART_INF_F, l0 = 0.f, l1 = 0.f;

    const int row0 = tile * 128 + w * 16 + g;   // warp's first row (this thread)
    const int lim0 = row0 >> 2;
    const int lim1 = (row0 + 8) >> 2;

    const int nch = (32 * tile + 95) >> 6;

    // K-load geometry: lane-> (j = lane&7 + 8*w, d = lane>>3 + 4i), bank-perfect
    const int kj = (lane & 7) + 8 * w;
    const int kd = lane >> 3;

    for (int c = 0; c < nch; c++) {
        const int k0 = c * 64;
        __syncthreads();    // protect Ks/Vs from previous iteration readers

        #pragma unroll
        for (int i = 0; i < 16; i++) {
            const int d = kd + i * 4;
            Ks[d * 72 + kj] = f2tf32(Kh[kvbase + (size_t)(k0 + kj) * DD + d]);
        }
        #pragma unroll
        for (int i = 0; i < 4; i++) {
            const int idx = tid + i * 256;
            const int j = idx >> 4, d4 = (idx & 15) << 2;
            const float4 v = *(const float4*)(Vh + kvbase + (size_t)(k0 + j) * DD + d4);
            uint4 u;
            u.x = f2tf32(v.x); u.y = f2tf32(v.y);
            u.z = f2tf32(v.z); u.w = f2tf32(v.w);
            *(uint4*)&Vs[j * 72 + d4] = u;
        }
        __syncthreads();

        // S = Q @ K^T  (warp rows w*16..w*16+15, all 64 key columns)
        float pf[8][4];
        #pragma unroll
        for (int ni = 0; ni < 8; ni++)
            #pragma unroll
            for (int r = 0; r < 4; r++) pf[ni][r] = 0.f;

        #pragma unroll
        for (int ks = 0; ks < 8; ks++) {
            const int kk = ks * 8;
            const int mb = w * 16;
            uint32_t af[4];
            af[0] = Qs[(mb + g) * 68 + kk + t];
            af[1] = Qs[(mb + g + 8) * 68 + kk + t];
            af[2] = Qs[(mb + g) * 68 + kk + t + 4];
            af[3] = Qs[(mb + g + 8) * 68 + kk + t + 4];
            #pragma unroll
            for (int ni = 0; ni < 8; ni++) {
                uint32_t bf[2];
                bf[0] = Ks[(kk + t) * 72 + ni * 8 + g];
                bf[1] = Ks[(kk + t + 4) * 72 + ni * 8 + g];
                mma_tf32(pf[ni], af, bf);
            }
        }

        // mask (diagonal chunk only) + online softmax
        if (c == nch - 1) {
            #pragma unroll
            for (int ni = 0; ni < 8; ni++) {
                const int j = k0 + ni * 8 + 2 * t;
                if (j > lim0)     pf[ni][0] = -CUDART_INF_F;
                if (j + 1 > lim0) pf[ni][1] = -CUDART_INF_F;
                if (j > lim1)     pf[ni][2] = -CUDART_INF_F;
                if (j + 1 > lim1) pf[ni][3] = -CUDART_INF_F;
            }
        }

        float mx0 = -CUDART_INF_F, mx1 = -CUDART_INF_F;
        #pragma unroll
        for (int ni = 0; ni < 8; ni++) {
            mx0 = fmaxf(mx0, fmaxf(pf[ni][0], pf[ni][1]));
            mx1 = fmaxf(mx1, fmaxf(pf[ni][2], pf[ni][3]));
        }
        mx0 = fmaxf(mx0, __shfl_xor_sync(0xffffffffu, mx0, 1));
        mx0 = fmaxf(mx0, __shfl_xor_sync(0xffffffffu, mx0, 2));
        mx1 = fmaxf(mx1, __shfl_xor_sync(0xffffffffu, mx1, 1));
        mx1 = fmaxf(mx1, __shfl_xor_sync(0xffffffffu, mx1, 2));

        const float mn0 = fmaxf(m0, mx0), mn1 = fmaxf(m1, mx1);
        const float al0 = __expf(m0 - mn0), al1 = __expf(m1 - mn1);
        m0 = mn0; m1 = mn1;

        float rs0 = 0.f, rs1 = 0.f;
        #pragma unroll
        for (int ni = 0; ni < 8; ni++) {
            pf[ni][0] = __expf(pf[ni][0] - mn0);
            pf[ni][1] = __expf(pf[ni][1] - mn0);
            pf[ni][2] = __expf(pf[ni][2] - mn1);
            pf[ni][3] = __expf(pf[ni][3] - mn1);
            rs0 += pf[ni][0] + pf[ni][1];
            rs1 += pf[ni][2] + pf[ni][3];
        }
        rs0 += __shfl_xor_sync(0xffffffffu, rs0, 1);
        rs0 += __shfl_xor_sync(0xffffffffu, rs0, 2);
        rs1 += __shfl_xor_sync(0xffffffffu, rs1, 1);
        rs1 += __shfl_xor_sync(0xffffffffu, rs1, 2);
        l0 = l0 * al0 + rs0;
        l1 = l1 * al1 + rs1;

        #pragma unroll
        for (int ni = 0; ni < 8; ni++) {
            oacc[ni][0] *= al0; oacc[ni][1] *= al0;
            oacc[ni][2] *= al1; oacc[ni][3] *= al1;
        }

        // O += P @ V : remap C-frag(P) -> A-frag via shuffles, per k-tile
        const int s1 = (g << 2) | (t >> 1);
        const int s2 = s1 + 2;
        const bool odd = (t & 1);
        #pragma unroll
        for (int kt = 0; kt < 8; kt++) {
            const float v00 = __shfl_sync(0xffffffffu, pf[kt][0], s1);
            const float v01 = __shfl_sync(0xffffffffu, pf[kt][1], s1);
            const float v10 = __shfl_sync(0xffffffffu, pf[kt][2], s1);
            const float v11 = __shfl_sync(0xffffffffu, pf[kt][3], s1);
            const float w00 = __shfl_sync(0xffffffffu, pf[kt][0], s2);
            const float w01 = __shfl_sync(0xffffffffu, pf[kt][1], s2);
            const float w10 = __shfl_sync(0xffffffffu, pf[kt][2], s2);
            const float w11 = __shfl_sync(0xffffffffu, pf[kt][3], s2);
            uint32_t a[4];
            a[0] = f2tf32(odd ? v01 : v00);
            a[1] = f2tf32(odd ? v11 : v10);
            a[2] = f2tf32(odd ? w01 : w00);
            a[3] = f2tf32(odd ? w11 : w10);
            #pragma unroll
            for (int ni = 0; ni < 8; ni++) {
                uint32_t bf[2];
                bf[0] = Vs[(kt * 8 + t) * 72 + ni * 8 + g];
                bf[1] = Vs[(kt * 8 + t + 4) * 72 + ni * 8 + g];
                mma_tf32(oacc[ni], a, bf);
            }
        }
    }

    // epilogue
    const float inv0 = 1.f / l0, inv1 = 1.f / l1;
    const int lr0 = w * 16 + g;
    #pragma unroll
    for (int ni = 0; ni < 8; ni++) {
        const int cc = ni * 8 + 2 * t;
        *(float2*)(O + qbase + (size_t)lr0 * DD + cc) =
            make_float2(oacc[ni][0] * inv0, oacc[ni][1] * inv0);
        *(float2*)(O + qbase + (size_t)(lr0 + 8) * DD + cc) =
            make_float2(oacc[ni][2] * inv1, oacc[ni][3] * inv1);
    }
}

// ---------------------------------------------------------------------------
// LayerNorm over last dim (512). One block per row.
// ---------------------------------------------------------------------------
__global__ void __launch_bounds__(256) ln_kernel(
    const float* __restrict__ X, const float* __restrict__ gamma,
    const float* __restrict__ beta, float* __restrict__ Y)
{
    __shared__ float red[16];
    __shared__ float mv[2];

    const int row = blockIdx.x;
    const int tid = threadIdx.x;
    const float* x = X + (size_t)row * DD;

    const float2 v = *(const float2*)(x + tid * 2);
    float s = v.x + v.y;
    float sq = v.x * v.x + v.y * v.y;

    #pragma unroll
    for (int off = 16; off > 0; off >>= 1) {
        s += __shfl_xor_sync(0xffffffffu, s, off);
        sq += __shfl_xor_sync(0xffffffffu, sq, off);
    }
    const int wid = tid >> 5;
    if ((tid & 31) == 0) { red[wid] = s; red[8 + wid] = sq; }
    __syncthreads();
    if (tid == 0) {
        float S = 0.f, SQ = 0.f;
        #pragma unroll
        for (int ww = 0; ww < 8; ww++) { S += red[ww]; SQ += red[8 + ww]; }
        const float mean = S * (1.f / DD);
        const float var = SQ * (1.f / DD) - mean * mean;
        mv[0] = mean;
        mv[1] = rsqrtf(var + LN_EPS);
    }
    __syncthreads();
    const float mean = mv[0], r = mv[1];

    const float2 gm = *(const float2*)(gamma + tid * 2);
    const float2 be = *(const float2*)(beta + tid * 2);
    float2 out;
    out.x = (v.x - mean) * r * gm.x + be.x;
    out.y = (v.y - mean) * r * gm.y + be.y;
    *(float2*)(Y + (size_t)row * DD + tid * 2) = out;
}

// ---------------------------------------------------------------------------
// Launch
// ---------------------------------------------------------------------------
extern "C" void kernel_launch(void* const* d_in, const int* in_sizes, int n_in,
                              void* d_out, int out_size)
{
    (void)in_sizes; (void)n_in; (void)out_size;

    const float* q     = (const float*)d_in[0];
    const float* kv    = (const float*)d_in[1];
    const float* Wq    = (const float*)d_in[2];
    const float* Wk    = (const float*)d_in[3];
    const float* Wv    = (const float*)d_in[4];
    const float* Wo    = (const float*)d_in[5];
    const float* bo    = (const float*)d_in[6];
    const float* gamma = (const float*)d_in[7];
    const float* beta  = (const float*)d_in[8];
    float* out = (float*)d_out;

    float *qh, *kh, *vh, *attn, *norm;
    cudaGetSymbolAddress((void**)&qh,   g_qh);
    cudaGetSymbolAddress((void**)&kh,   g_kh);
    cudaGetSymbolAddress((void**)&vh,   g_vh);
    cudaGetSymbolAddress((void**)&attn, g_attn);
    cudaGetSymbolAddress((void**)&norm, g_norm);

    cudaFuncSetAttribute(attn_mma,
                         cudaFuncAttributeMaxDynamicSharedMemorySize,
                         ATTN_SMEM_BYTES);

    const int MQ = BB * NQ;    // 8192
    const int MK = BB * NKV;   // 2048

    // Q projection
    {
        dim3 grid(DD / 128, MQ / 128, 1);
        gemm_tf32<false><<<grid, 256>>>(q, Wq, nullptr, nullptr, qh, nullptr,
                                        MQ, DD, DD);
    }
    // K and V projections in one launch (z selects)
    {
        dim3 grid(DD / 128, MK / 128, 2);
        gemm_tf32<false><<<grid, 256>>>(kv, Wk, Wv, nullptr, kh, vh,
                                        MK, DD, DD);
    }
    // Attention
    {
        dim3 grid(NQ / 128, HH, BB);
        attn_mma<<<grid, 256, ATTN_SMEM_BYTES>>>(qh, kh, vh, attn);
    }
    // LayerNorm
    ln_kernel<<<MQ, 256>>>(attn, gamma, beta, norm);
    // Output projection + bias
    {
        dim3 grid(DD / 128, MQ / 128, 1);
        gemm_tf32<true><<<grid, 256>>>(norm, Wo, nullptr, bo, out, nullptr,
                                       MQ, DD, DD);
    }
}

// round 6
// speedup vs baseline: 4.9649x; 1.5335x over previous
#include <cuda_runtime.h>
#include <cuda_fp16.h>
#include <math_constants.h>
#include <cstdint>
#include <cstddef>

#define BB 2
#define NQ 4096
#define NKV 1024
#define DD 512
#define HH 8
#define DH 64
#define LN_EPS 1e-5f

// ---------------------------------------------------------------------------
// Scratch
// ---------------------------------------------------------------------------
__device__ float g_qh[BB * NQ * DD];
__device__ float g_kh[BB * NKV * DD];
__device__ float g_vh[BB * NKV * DD];
__device__ float g_attn[BB * NQ * DD];
__device__ float g_norm[BB * NQ * DD];
__device__ __half g_wt[4 * DD * DD];   // W^T, fp16, [n][k] k-contiguous

// ---------------------------------------------------------------------------
// helpers
// ---------------------------------------------------------------------------
__device__ __forceinline__ uint32_t packh2(float lo, float hi) {
    uint32_t r;
    asm("cvt.rn.f16x2.f32 %0, %1, %2;" : "=r"(r) : "f"(hi), "f"(lo));
    return r;
}

__device__ __forceinline__ void mma_f16(float d[4], const uint32_t a[4],
                                        const uint32_t b[2]) {
    asm("mma.sync.aligned.m16n8k16.row.col.f32.f16.f16.f32 "
        "{%0,%1,%2,%3},{%4,%5,%6,%7},{%8,%9},{%0,%1,%2,%3};"
        : "+f"(d[0]), "+f"(d[1]), "+f"(d[2]), "+f"(d[3])
        : "r"(a[0]), "r"(a[1]), "r"(a[2]), "r"(a[3]), "r"(b[0]), "r"(b[1]));
}

// ---------------------------------------------------------------------------
// Weight transpose + fp16 convert: Wt[z][n][k] = fp16(W_z[k][n])
// ---------------------------------------------------------------------------
__global__ void __launch_bounds__(256) transpose_w(
    const float* __restrict__ Wq, const float* __restrict__ Wk,
    const float* __restrict__ Wv, const float* __restrict__ Wo,
    __half* __restrict__ Wt)
{
    __shared__ float t[32][33];
    const int z = blockIdx.z;
    const float* W = (z == 0) ? Wq : (z == 1) ? Wk : (z == 2) ? Wv : Wo;
    __half* T = Wt + (size_t)z * DD * DD;
    const int tx = threadIdx.x, ty = threadIdx.y;
    const int kb = blockIdx.x * 32, nb = blockIdx.y * 32;
    #pragma unroll
    for (int j = 0; j < 4; j++)
        t[ty + j * 8][tx] = W[(size_t)(kb + ty + j * 8) * DD + nb + tx];
    __syncthreads();
    #pragma unroll
    for (int j = 0; j < 4; j++)
        T[(size_t)(nb + ty + j * 8) * DD + kb + tx] =
            __float2half_rn(t[tx][ty + j * 8]);
}

// ---------------------------------------------------------------------------
// fp16 GEMM: C[M,512] = A[M,512] @ W (+bias), Wt = W^T fp16 [n][k].
// 128x128 block, BK=32, 256 threads, warps 4(M)x2(N), warp tile 32x64.
// As/Bs: [128 rows][20 words] (32 halves data + pad). m16n8k16 mma.
// blockIdx.z selects (Wt0,C0)/(Wt1,C1).
// ---------------------------------------------------------------------------
template <bool BIAS>
__global__ void __launch_bounds__(256) gemm_f16(
    const float* __restrict__ A, const __half* __restrict__ Wt0,
    const __half* __restrict__ Wt1, const float* __restrict__ bias,
    float* __restrict__ C0, float* __restrict__ C1, int M)
{
    __shared__ uint32_t As[128 * 20];
    __shared__ uint32_t Bs[128 * 20];

    const __half* __restrict__ Wt = blockIdx.z ? Wt1 : Wt0;
    float* __restrict__ C = blockIdx.z ? C1 : C0;

    const int tid = threadIdx.x;
    const int lane = tid & 31;
    const int g = lane >> 2, t = lane & 3;
    const int w = tid >> 5;
    const int wm = w >> 1, wn = w & 1;
    const int row0 = blockIdx.y * 128, col0 = blockIdx.x * 128;

    // A loader: 128 rows x 8 float4 = 1024 units, 4/thread
    const int ar = tid >> 3;            // + i*32
    const int af4 = tid & 7;
    // B loader: 128 rows x 4 uint4(8 halves) = 512 units, 2/thread
    const int br = tid >> 2;            // + i*64
    const int bf = tid & 3;

    float4 aR[4];
    uint4 bR[2];

    auto loadA = [&](int k0) {
        #pragma unroll
        for (int i = 0; i < 4; i++)
            aR[i] = *(const float4*)(A + (size_t)(row0 + ar + i * 32) * DD + k0 + af4 * 4);
    };
    auto loadB = [&](int k0) {
        #pragma unroll
        for (int i = 0; i < 2; i++)
            bR[i] = *(const uint4*)(Wt + (size_t)(col0 + br + i * 64) * DD + k0 + bf * 8);
    };

    float acc[2][8][4];
    #pragma unroll
    for (int mi = 0; mi < 2; mi++)
        #pragma unroll
        for (int ni = 0; ni < 8; ni++)
            #pragma unroll
            for (int r = 0; r < 4; r++) acc[mi][ni][r] = 0.f;

    loadA(0);
    loadB(0);

    for (int k0 = 0; k0 < DD; k0 += 32) {
        #pragma unroll
        for (int i = 0; i < 4; i++) {
            const uint32_t w0 = packh2(aR[i].x, aR[i].y);
            const uint32_t w1 = packh2(aR[i].z, aR[i].w);
            *(uint2*)&As[(ar + i * 32) * 20 + af4 * 2] = make_uint2(w0, w1);
        }
        #pragma unroll
        for (int i = 0; i < 2; i++)
            *(uint4*)&Bs[(br + i * 64) * 20 + bf * 4] = bR[i];
        __syncthreads();

        if (k0 + 32 < DD) { loadA(k0 + 32); loadB(k0 + 32); }

        #pragma unroll
        for (int ks = 0; ks < 2; ks++) {
            const int ko = ks * 8;
            uint32_t af[2][4];
            #pragma unroll
            for (int mi = 0; mi < 2; mi++) {
                const int mb = wm * 32 + mi * 16;
                af[mi][0] = As[(mb + g) * 20 + ko + t];
                af[mi][1] = As[(mb + g + 8) * 20 + ko + t];
                af[mi][2] = As[(mb + g) * 20 + ko + t + 4];
                af[mi][3] = As[(mb + g + 8) * 20 + ko + t + 4];
            }
            #pragma unroll
            for (int ni = 0; ni < 8; ni++) {
                const int nb = wn * 64 + ni * 8;
                uint32_t bf2[2];
                bf2[0] = Bs[(nb + g) * 20 + ko + t];
                bf2[1] = Bs[(nb + g) * 20 + ko + t + 4];
                mma_f16(acc[0][ni], af[0], bf2);
                mma_f16(acc[1][ni], af[1], bf2);
            }
        }
        __syncthreads();
    }

    #pragma unroll
    for (int mi = 0; mi < 2; mi++) {
        const int rr0 = row0 + wm * 32 + mi * 16 + g;
        #pragma unroll
        for (int ni = 0; ni < 8; ni++) {
            const int cc = col0 + wn * 64 + ni * 8 + 2 * t;
            float2 v0 = make_float2(acc[mi][ni][0], acc[mi][ni][1]);
            float2 v1 = make_float2(acc[mi][ni][2], acc[mi][ni][3]);
            if (BIAS) {
                const float2 bv = *(const float2*)(bias + cc);
                v0.x += bv.x; v0.y += bv.y;
                v1.x += bv.x; v1.y += bv.y;
            }
            *(float2*)(C + (size_t)rr0 * DD + cc) = v0;
            *(float2*)(C + (size_t)(rr0 + 8) * DD + cc) = v1;
        }
    }
}

// ---------------------------------------------------------------------------
// Flash attention, fp16 mma. Block = 128 queries x (b,h). 8 warps x 16 rows.
// Qs[128][36w] (pre-scaled 1/8), Ks[64][36w] natural, Vs[32][68w] = key-pair
// interleaved half2. S: m16n8k16 x (4 kt x 8 ni). P@V: C-frag packs directly
// into A-frags (same lane), B-reg = single b32 LDS. Diagonal-chunk-only mask.
// ---------------------------------------------------------------------------
__global__ void __launch_bounds__(256) attn_f16(
    const float* __restrict__ Qh, const float* __restrict__ Kh,
    const float* __restrict__ Vh, float* __restrict__ O)
{
    __shared__ uint32_t Qs[128 * 36];
    __shared__ uint32_t Ks[64 * 36];
    __shared__ uint32_t Vs[32 * 68];

    const int tile = (NQ / 128 - 1) - blockIdx.x;   // big tiles first
    const int h = blockIdx.y, b = blockIdx.z;
    const int tid = threadIdx.x;
    const int lane = tid & 31;
    const int g = lane >> 2, t = lane & 3;
    const int w = tid >> 5;

    const size_t qbase = ((size_t)b * NQ + (size_t)tile * 128) * DD + (size_t)h * DH;
    const size_t kvbase = (size_t)b * NKV * DD + (size_t)h * DH;

    // Q tile (scaled 1/8, fp16)
    #pragma unroll
    for (int i = 0; i < 8; i++) {
        const int idx = tid + i * 256;
        const int r = idx >> 4, c4 = idx & 15;
        const float4 v = *(const float4*)(Qh + qbase + (size_t)r * DD + c4 * 4);
        const uint32_t w0 = packh2(v.x * 0.125f, v.y * 0.125f);
        const uint32_t w1 = packh2(v.z * 0.125f, v.w * 0.125f);
        *(uint2*)&Qs[r * 36 + c4 * 2] = make_uint2(w0, w1);
    }

    float oacc[8][4];
    #pragma unroll
    for (int ni = 0; ni < 8; ni++)
        #pragma unroll
        for (int r = 0; r < 4; r++) oacc[ni][r] = 0.f;
    float m0 = -CUDART_INF_F, m1 = -CUDART_INF_F, l0 = 0.f, l1 = 0.f;

    const int row0 = tile * 128 + w * 16 + g;
    const int lim0 = row0 >> 2;
    const int lim1 = (row0 + 8) >> 2;
    const int nch = (32 * tile + 95) >> 6;

    for (int c = 0; c < nch; c++) {
        const int k0 = c * 64;
        __syncthreads();    // protect Ks/Vs from previous readers

        // K tile natural (fp16)
        #pragma unroll
        for (int i = 0; i < 4; i++) {
            const int idx = tid + i * 256;
            const int r = idx >> 4, c4 = idx & 15;
            const float4 v = *(const float4*)(Kh + kvbase + (size_t)(k0 + r) * DD + c4 * 4);
            const uint32_t w0 = packh2(v.x, v.y);
            const uint32_t w1 = packh2(v.z, v.w);
            *(uint2*)&Ks[r * 36 + c4 * 2] = make_uint2(w0, w1);
        }
        // V tile, key-pair interleaved: Vs[jp][d] = half2(V[2jp][d], V[2jp+1][d])
        #pragma unroll
        for (int i = 0; i < 2; i++) {
            const int idx = tid + i * 256;
            const int jp = idx >> 4, d4 = idx & 15;
            const float4 r0 = *(const float4*)(Vh + kvbase + (size_t)(k0 + 2 * jp) * DD + d4 * 4);
            const float4 r1 = *(const float4*)(Vh + kvbase + (size_t)(k0 + 2 * jp + 1) * DD + d4 * 4);
            uint4 u;
            u.x = packh2(r0.x, r1.x); u.y = packh2(r0.y, r1.y);
            u.z = packh2(r0.z, r1.z); u.w = packh2(r0.w, r1.w);
            *(uint4*)&Vs[jp * 68 + d4 * 4] = u;
        }
        __syncthreads();

        // S = Q @ K^T
        float pf[8][4];
        #pragma unroll
        for (int ni = 0; ni < 8; ni++)
            #pragma unroll
            for (int r = 0; r < 4; r++) pf[ni][r] = 0.f;

        const int mb = w * 16;
        #pragma unroll
        for (int kt = 0; kt < 4; kt++) {
            const int ko = kt * 8;
            uint32_t af[4];
            af[0] = Qs[(mb + g) * 36 + ko + t];
            af[1] = Qs[(mb + g + 8) * 36 + ko + t];
            af[2] = Qs[(mb + g) * 36 + ko + t + 4];
            af[3] = Qs[(mb + g + 8) * 36 + ko + t + 4];
            #pragma unroll
            for (int ni = 0; ni < 8; ni++) {
                uint32_t bf2[2];
                bf2[0] = Ks[(ni * 8 + g) * 36 + ko + t];
                bf2[1] = Ks[(ni * 8 + g) * 36 + ko + t + 4];
                mma_f16(pf[ni], af, bf2);
            }
        }

        // mask (diagonal chunk only) + online softmax
        if (c == nch - 1) {
            #pragma unroll
            for (int ni = 0; ni < 8; ni++) {
                const int j = k0 + ni * 8 + 2 * t;
                if (j > lim0)     pf[ni][0] = -CUDART_INF_F;
                if (j + 1 > lim0) pf[ni][1] = -CUDART_INF_F;
                if (j > lim1)     pf[ni][2] = -CUDART_INF_F;
                if (j + 1 > lim1) pf[ni][3] = -CUDART_INF_F;
            }
        }

        float mx0 = -CUDART_INF_F, mx1 = -CUDART_INF_F;
        #pragma unroll
        for (int ni = 0; ni < 8; ni++) {
            mx0 = fmaxf(mx0, fmaxf(pf[ni][0], pf[ni][1]));
            mx1 = fmaxf(mx1, fmaxf(pf[ni][2], pf[ni][3]));
        }
        mx0 = fmaxf(mx0, __shfl_xor_sync(0xffffffffu, mx0, 1));
        mx0 = fmaxf(mx0, __shfl_xor_sync(0xffffffffu, mx0, 2));
        mx1 = fmaxf(mx1, __shfl_xor_sync(0xffffffffu, mx1, 1));
        mx1 = fmaxf(mx1, __shfl_xor_sync(0xffffffffu, mx1, 2));

        const float mn0 = fmaxf(m0, mx0), mn1 = fmaxf(m1, mx1);
        const float al0 = __expf(m0 - mn0), al1 = __expf(m1 - mn1);
        m0 = mn0; m1 = mn1;

        float rs0 = 0.f, rs1 = 0.f;
        #pragma unroll
        for (int ni = 0; ni < 8; ni++) {
            pf[ni][0] = __expf(pf[ni][0] - mn0);
            pf[ni][1] = __expf(pf[ni][1] - mn0);
            pf[ni][2] = __expf(pf[ni][2] - mn1);
            pf[ni][3] = __expf(pf[ni][3] - mn1);
            rs0 += pf[ni][0] + pf[ni][1];
            rs1 += pf[ni][2] + pf[ni][3];
        }
        rs0 += __shfl_xor_sync(0xffffffffu, rs0, 1);
        rs0 += __shfl_xor_sync(0xffffffffu, rs0, 2);
        rs1 += __shfl_xor_sync(0xffffffffu, rs1, 1);
        rs1 += __shfl_xor_sync(0xffffffffu, rs1, 2);
        l0 = l0 * al0 + rs0;
        l1 = l1 * al1 + rs1;

        #pragma unroll
        for (int ni = 0; ni < 8; ni++) {
            oacc[ni][0] *= al0; oacc[ni][1] *= al0;
            oacc[ni][2] *= al1; oacc[ni][3] *= al1;
        }

        // O += P @ V : C-frag packs straight into A-frags, same lane
        #pragma unroll
        for (int kt = 0; kt < 4; kt++) {
            uint32_t a[4];
            a[0] = packh2(pf[2 * kt][0],     pf[2 * kt][1]);
            a[1] = packh2(pf[2 * kt][2],     pf[2 * kt][3]);
            a[2] = packh2(pf[2 * kt + 1][0], pf[2 * kt + 1][1]);
            a[3] = packh2(pf[2 * kt + 1][2], pf[2 * kt + 1][3]);
            const int jp0 = 8 * kt + t;
            #pragma unroll
            for (int ni = 0; ni < 8; ni++) {
                uint32_t bf2[2];
                bf2[0] = Vs[jp0 * 68 + ni * 8 + g];
                bf2[1] = Vs[(jp0 + 4) * 68 + ni * 8 + g];
                mma_f16(oacc[ni], a, bf2);
            }
        }
    }

    const float inv0 = 1.f / l0, inv1 = 1.f / l1;
    const int lr0 = w * 16 + g;
    #pragma unroll
    for (int ni = 0; ni < 8; ni++) {
        const int cc = ni * 8 + 2 * t;
        *(float2*)(O + qbase + (size_t)lr0 * DD + cc) =
            make_float2(oacc[ni][0] * inv0, oacc[ni][1] * inv0);
        *(float2*)(O + qbase + (size_t)(lr0 + 8) * DD + cc) =
            make_float2(oacc[ni][2] * inv1, oacc[ni][3] * inv1);
    }
}

// ---------------------------------------------------------------------------
// LayerNorm over last dim (512). One block per row.
// ---------------------------------------------------------------------------
__global__ void __launch_bounds__(256) ln_kernel(
    const float* __restrict__ X, const float* __restrict__ gamma,
    const float* __restrict__ beta, float* __restrict__ Y)
{
    __shared__ float red[16];
    __shared__ float mv[2];

    const int row = blockIdx.x;
    const int tid = threadIdx.x;
    const float* x = X + (size_t)row * DD;

    const float2 v = *(const float2*)(x + tid * 2);
    float s = v.x + v.y;
    float sq = v.x * v.x + v.y * v.y;

    #pragma unroll
    for (int off = 16; off > 0; off >>= 1) {
        s += __shfl_xor_sync(0xffffffffu, s, off);
        sq += __shfl_xor_sync(0xffffffffu, sq, off);
    }
    const int wid = tid >> 5;
    if ((tid & 31) == 0) { red[wid] = s; red[8 + wid] = sq; }
    __syncthreads();
    if (tid == 0) {
        float S = 0.f, SQ = 0.f;
        #pragma unroll
        for (int ww = 0; ww < 8; ww++) { S += red[ww]; SQ += red[8 + ww]; }
        const float mean = S * (1.f / DD);
        const float var = SQ * (1.f / DD) - mean * mean;
        mv[0] = mean;
        mv[1] = rsqrtf(var + LN_EPS);
    }
    __syncthreads();
    const float mean = mv[0], r = mv[1];

    const float2 gm = *(const float2*)(gamma + tid * 2);
    const float2 be = *(const float2*)(beta + tid * 2);
    float2 out;
    out.x = (v.x - mean) * r * gm.x + be.x;
    out.y = (v.y - mean) * r * gm.y + be.y;
    *(float2*)(Y + (size_t)row * DD + tid * 2) = out;
}

// ---------------------------------------------------------------------------
// Launch
// ---------------------------------------------------------------------------
extern "C" void kernel_launch(void* const* d_in, const int* in_sizes, int n_in,
                              void* d_out, int out_size)
{
    (void)in_sizes; (void)n_in; (void)out_size;

    const float* q     = (const float*)d_in[0];
    const float* kv    = (const float*)d_in[1];
    const float* Wq    = (const float*)d_in[2];
    const float* Wk    = (const float*)d_in[3];
    const float* Wv    = (const float*)d_in[4];
    const float* Wo    = (const float*)d_in[5];
    const float* bo    = (const float*)d_in[6];
    const float* gamma = (const float*)d_in[7];
    const float* beta  = (const float*)d_in[8];
    float* out = (float*)d_out;

    float *qh, *kh, *vh, *attn, *norm;
    __half* wt;
    cudaGetSymbolAddress((void**)&qh,   g_qh);
    cudaGetSymbolAddress((void**)&kh,   g_kh);
    cudaGetSymbolAddress((void**)&vh,   g_vh);
    cudaGetSymbolAddress((void**)&attn, g_attn);
    cudaGetSymbolAddress((void**)&norm, g_norm);
    cudaGetSymbolAddress((void**)&wt,   g_wt);

    const __half* wtq = wt;
    const __half* wtk = wt + 1 * DD * DD;
    const __half* wtv = wt + 2 * DD * DD;
    const __half* wto = wt + 3 * DD * DD;

    // Transpose + fp16-convert all weights
    {
        dim3 grid(DD / 32, DD / 32, 4);
        transpose_w<<<grid, dim3(32, 8)>>>(Wq, Wk, Wv, Wo, wt);
    }
    // Q projection: 8192 x 512
    {
        dim3 grid(DD / 128, (BB * NQ) / 128, 1);
        gemm_f16<false><<<grid, 256>>>(q, wtq, nullptr, nullptr, qh, nullptr, BB * NQ);
    }
    // K and V projections: 2048 x 512, z selects
    {
        dim3 grid(DD / 128, (BB * NKV) / 128, 2);
        gemm_f16<false><<<grid, 256>>>(kv, wtk, wtv, nullptr, kh, vh, BB * NKV);
    }
    // Attention
    {
        dim3 grid(NQ / 128, HH, BB);
        attn_f16<<<grid, 256>>>(qh, kh, vh, attn);
    }
    // LayerNorm
    ln_kernel<<<BB * NQ, 256>>>(attn, gamma, beta, norm);
    // Output projection + bias
    {
        dim3 grid(DD / 128, (BB * NQ) / 128, 1);
        gemm_f16<true><<<grid, 256>>>(norm, wto, nullptr, bo, out, nullptr, BB * NQ);
    }
}